// round 7
// baseline (speedup 1.0000x reference)
#include <cuda_runtime.h>

// IIR filterbank (DF2T, order 4), overlap-save + warp-transposed smem staging.
// x: (128, 4, 65536) f32; b,a: (4,5) f32; out same shape as x.
//
// R6 findings: dur 65.6us, DRAM 55%, occ 20.3% (= launch limit of 2048 warps),
// issue 24.7% -> still latency-bound. HBM moved only ~266MB of the 304MB
// traffic: warmup re-reads are L2-served (L2 at 28%), so extra chunk overlap
// is cheap. rel_err identical across R5/R6 -> rounding-dominated, WARMUP=192
// has big margin.
// Fix: CHUNK_L 512->256 (4096 warps, 512 CTAs, all resident in one wave at
// 37KB smem -> 6 CTAs/SM).

#define T_LEN     65536
#define CHUNK_L   256
#define WARMUP    192
#define TILE      32          // floats per row per staged tile
#define RSTRIDE   36          // padded row stride (words): conflict-free 16B ops
#define WPB       8           // warps per block
#define THREADS   256
#define WARPS_PER_CH  ((T_LEN / CHUNK_L) / 32)   // 8

// DF2T step: y = b0*x + z0; z_i = b_{i+1}*x + z_{i+1} - a_{i+1}*y
#define IIR_STEP(xn, yn) do {                              \
        float xv_ = (xn);                                  \
        float y_  = fmaf(b0, xv_, z0);                     \
        z0 = fmaf(na1, y_, fmaf(b1, xv_, z1));             \
        z1 = fmaf(na2, y_, fmaf(b2, xv_, z2));             \
        z2 = fmaf(na3, y_, fmaf(b3, xv_, z3));             \
        z3 = fmaf(na4, y_, b4 * xv_);                      \
        (yn) = y_;                                         \
    } while (0)

__global__ void __launch_bounds__(THREADS)
iir_filterbank_kernel(const float* __restrict__ x,
                      const float* __restrict__ bc,
                      const float* __restrict__ ac,
                      float* __restrict__ y)
{
    __shared__ float sm_all[WPB][32 * RSTRIDE];   // 4608B/warp, 36.9KB/block

    const int lane = threadIdx.x & 31;
    const int wib  = threadIdx.x >> 5;
    const int w    = blockIdx.x * WPB + wib;          // global warp id
    const int channel     = w / WARPS_PER_CH;         // 8 warps per channel
    const int first_chunk = (w % WARPS_PER_CH) * 32;  // warp covers 32 chunks
    const int f    = channel & 3;

    float* sm = sm_all[wib];

    // Coefficients (a0 == 1 in dataset; normalize anyway).
    float inv = 1.0f / __ldg(&ac[f*5+0]);
    float b0  =  __ldg(&bc[f*5+0]) * inv;
    float b1  =  __ldg(&bc[f*5+1]) * inv;
    float b2  =  __ldg(&bc[f*5+2]) * inv;
    float b3  =  __ldg(&bc[f*5+3]) * inv;
    float b4  =  __ldg(&bc[f*5+4]) * inv;
    float na1 = -__ldg(&ac[f*5+1]) * inv;
    float na2 = -__ldg(&ac[f*5+2]) * inv;
    float na3 = -__ldg(&ac[f*5+3]) * inv;
    float na4 = -__ldg(&ac[f*5+4]) * inv;

    const long long ch_base = (long long)channel * T_LEN;
    const int sub   = lane & 7;    // 16B slot within a 128B row
    const int rbase = lane >> 3;   // row group 0..3

    float z0 = 0.f, z1 = 0.f, z2 = 0.f, z3 = 0.f;

    // ---- Warmup: 6 staged tiles of 32 samples (state convergence only) ----
    #pragma unroll 1
    for (int wt = 0; wt < WARMUP / TILE; ++wt) {
        float4 v[8];
        #pragma unroll
        for (int s = 0; s < 8; ++s) {
            int r = s * 4 + rbase;
            long long g = ch_base + (long long)(first_chunk + r) * CHUNK_L
                          - WARMUP + wt * TILE + sub * 4;
            if (first_chunk + r == 0) g += WARMUP;  // chunk 0: no prefix (avoids OOB)
            v[s] = __ldg((const float4*)(x + g));
        }
        #pragma unroll
        for (int s = 0; s < 8; ++s) {
            int r = s * 4 + rbase;
            *(float4*)&sm[r * RSTRIDE + sub * 4] = v[s];
        }
        __syncwarp();
        #pragma unroll
        for (int i = 0; i < 8; ++i) {
            float4 u = *(const float4*)&sm[lane * RSTRIDE + i * 4];
            float sink;
            IIR_STEP(u.x, sink); IIR_STEP(u.y, sink);
            IIR_STEP(u.z, sink); IIR_STEP(u.w, sink);
            (void)sink;
        }
        __syncwarp();  // cross-lane: reads done before next stage-in
    }
    // The lane owning chunk 0 starts from the true zero state (exact).
    if (first_chunk == 0 && lane == 0) { z0 = z1 = z2 = z3 = 0.f; }

    // ---- Main: 8 staged tiles of 32 samples ----
    #pragma unroll 1
    for (int t = 0; t < CHUNK_L / TILE; ++t) {
        const long long toff = (long long)t * TILE + sub * 4;
        float4 v[8];
        #pragma unroll
        for (int s = 0; s < 8; ++s) {       // coalesced: 1 wavefront / 128B
            int r = s * 4 + rbase;
            long long g = ch_base + (long long)(first_chunk + r) * CHUNK_L + toff;
            v[s] = __ldg((const float4*)(x + g));
        }
        #pragma unroll
        for (int s = 0; s < 8; ++s) {       // transpose into smem
            int r = s * 4 + rbase;
            *(float4*)&sm[r * RSTRIDE + sub * 4] = v[s];
        }
        __syncwarp();

        float4 o[8];
        #pragma unroll
        for (int i = 0; i < 8; ++i) {       // own row: conflict-free LDS.128
            float4 u = *(const float4*)&sm[lane * RSTRIDE + i * 4];
            IIR_STEP(u.x, o[i].x); IIR_STEP(u.y, o[i].y);
            IIR_STEP(u.z, o[i].z); IIR_STEP(u.w, o[i].w);
        }
        #pragma unroll
        for (int i = 0; i < 8; ++i)         // own row writes (no cross hazard)
            *(float4*)&sm[lane * RSTRIDE + i * 4] = o[i];
        __syncwarp();

        #pragma unroll
        for (int s = 0; s < 8; ++s) {       // gather + coalesced streaming store
            int r = s * 4 + rbase;
            float4 ov = *(const float4*)&sm[r * RSTRIDE + sub * 4];
            long long g = ch_base + (long long)(first_chunk + r) * CHUNK_L + toff;
            __stcs((float4*)(y + g), ov);
        }
        // No sync needed: next stage-in writes the exact addresses this lane
        // just read; cross-lane reads fenced by next iteration's __syncwarp.
    }
}

extern "C" void kernel_launch(void* const* d_in, const int* in_sizes, int n_in,
                              void* d_out, int out_size)
{
    const float* x = (const float*)d_in[0];   // (128, 4, 65536)
    const float* b = (const float*)d_in[1];   // (4, 5)
    const float* a = (const float*)d_in[2];   // (4, 5)
    float* y = (float*)d_out;

    int n_channels = in_sizes[0] / T_LEN;                 // 512
    int n_warps    = n_channels * WARPS_PER_CH;           // 4096
    int n_blocks   = n_warps / WPB;                       // 512

    iir_filterbank_kernel<<<n_blocks, THREADS>>>(x, b, a, y);
}

// round 8
// speedup vs baseline: 1.4523x; 1.4523x over previous
#include <cuda_runtime.h>

// IIR filterbank (DF2T, order 4), overlap-save + warp-transposed smem staging
// + software-pipelined (double-buffered) input tiles.
// x: (128, 4, 65536) f32; b,a: (4,5) f32; out same shape.
//
// R6: CHUNK_L=512 -> 65.6us (DRAM 55%, issue 25%): LDG->STS latency exposed.
// R7: CHUNK_L=256 REGRESSED to 80.4us (+27% tile work, warmup spilled to DRAM:
//     303MB vs 266MB). Occupancy lever exhausted -> revert to CHUNK_L=512 and
//     hide DRAM latency by prefetching tile i+1 during tile i's compute
//     (~650 issue-cycles of cover vs ~577-cycle DRAM latency).
//
// Warmup=192 from zero state: poles at r=0.9 -> state error ~1.7e-9; measured
// rel_err 2.07e-5 (rounding-dominated). Chunk 0 exact (state reset after warm).

#define T_LEN     65536
#define CHUNK_L   512
#define WARMUP    192
#define TILE      32
#define RSTRIDE   36          // padded row stride (words): conflict-free 16B ops
#define WPB       8
#define THREADS   256
#define WARPS_PER_CH  ((T_LEN / CHUNK_L) / 32)       // 4
#define NTILES    ((WARMUP + CHUNK_L) / TILE)        // 22
#define WTILES    (WARMUP / TILE)                    // 6

#define IIR_STEP(xn, yn) do {                              \
        float xv_ = (xn);                                  \
        float y_  = fmaf(b0, xv_, z0);                     \
        z0 = fmaf(na1, y_, fmaf(b1, xv_, z1));             \
        z1 = fmaf(na2, y_, fmaf(b2, xv_, z2));             \
        z2 = fmaf(na3, y_, fmaf(b3, xv_, z3));             \
        z3 = fmaf(na4, y_, b4 * xv_);                      \
        (yn) = y_;                                         \
    } while (0)

__global__ void __launch_bounds__(THREADS)
iir_filterbank_kernel(const float* __restrict__ x,
                      const float* __restrict__ bc,
                      const float* __restrict__ ac,
                      float* __restrict__ y)
{
    __shared__ float sm_all[WPB][32 * RSTRIDE];   // 4608B/warp, 36.9KB/block

    const int lane = threadIdx.x & 31;
    const int wib  = threadIdx.x >> 5;
    const int w    = blockIdx.x * WPB + wib;
    const int channel     = w / WARPS_PER_CH;
    const int first_chunk = (w % WARPS_PER_CH) * 32;
    const int f    = channel & 3;

    float* sm = sm_all[wib];

    float inv = 1.0f / __ldg(&ac[f*5+0]);
    float b0  =  __ldg(&bc[f*5+0]) * inv;
    float b1  =  __ldg(&bc[f*5+1]) * inv;
    float b2  =  __ldg(&bc[f*5+2]) * inv;
    float b3  =  __ldg(&bc[f*5+3]) * inv;
    float b4  =  __ldg(&bc[f*5+4]) * inv;
    float na1 = -__ldg(&ac[f*5+1]) * inv;
    float na2 = -__ldg(&ac[f*5+2]) * inv;
    float na3 = -__ldg(&ac[f*5+3]) * inv;
    float na4 = -__ldg(&ac[f*5+4]) * inv;

    const long long ch_base = (long long)channel * T_LEN;
    const int sub   = lane & 7;    // 16B slot within the 128B tile row
    const int rbase = lane >> 3;   // row group 0..3

    // Tile i of row r covers samples [chunk_r_start - WARMUP + i*32, +32).
    // Chunk 0 has no prefix: clamp its warmup reads into [0,192) (values are
    // irrelevant — its state is reset to zero after the warmup tiles).
#define LOAD_TILE(i, dst)                                                     \
    do {                                                                      \
        _Pragma("unroll")                                                     \
        for (int s_ = 0; s_ < 8; ++s_) {                                      \
            int r_ = s_ * 4 + rbase;                                          \
            long long g_ = ch_base + (long long)(first_chunk + r_) * CHUNK_L  \
                           - WARMUP + (long long)(i) * TILE + sub * 4;        \
            if (first_chunk + r_ == 0 && (i) < WTILES) g_ += WARMUP;          \
            (dst)[s_] = __ldg((const float4*)(x + g_));                       \
        }                                                                     \
    } while (0)

    float z0 = 0.f, z1 = 0.f, z2 = 0.f, z3 = 0.f;
    float4 v[8], vn[8];
    LOAD_TILE(0, v);

    #pragma unroll 1
    for (int i = 0; i < NTILES; ++i) {
        // Prefetch next tile: its latency hides under this tile's smem+FMA work.
        if (i + 1 < NTILES) LOAD_TILE(i + 1, vn);

        #pragma unroll
        for (int s = 0; s < 8; ++s)          // stage (transpose) into smem
            *(float4*)&sm[(s * 4 + rbase) * RSTRIDE + sub * 4] = v[s];
        __syncwarp();

        if (i < WTILES) {
            // Warmup: converge state only.
            #pragma unroll
            for (int j = 0; j < 8; ++j) {
                float4 u = *(const float4*)&sm[lane * RSTRIDE + j * 4];
                float sink;
                IIR_STEP(u.x, sink); IIR_STEP(u.y, sink);
                IIR_STEP(u.z, sink); IIR_STEP(u.w, sink);
                (void)sink;
            }
            if (i == WTILES - 1 && first_chunk == 0 && lane == 0) {
                z0 = z1 = z2 = z3 = 0.f;     // chunk 0: true zero initial state
            }
        } else {
            // Main: own-row LDS -> compute -> own-row STS (same lane, same
            // address: no sync needed between read and write).
            #pragma unroll
            for (int j = 0; j < 8; ++j) {
                float4 u = *(const float4*)&sm[lane * RSTRIDE + j * 4];
                float4 o;
                IIR_STEP(u.x, o.x); IIR_STEP(u.y, o.y);
                IIR_STEP(u.z, o.z); IIR_STEP(u.w, o.w);
                *(float4*)&sm[lane * RSTRIDE + j * 4] = o;
            }
            __syncwarp();
            #pragma unroll
            for (int s = 0; s < 8; ++s) {    // gather + coalesced streaming store
                int r = s * 4 + rbase;
                float4 ov = *(const float4*)&sm[r * RSTRIDE + sub * 4];
                long long g = ch_base + (long long)(first_chunk + r) * CHUNK_L
                              - WARMUP + (long long)i * TILE + sub * 4;
                __stcs((float4*)(y + g), ov);
            }
        }
        __syncwarp();                        // fence before next stage-in

        #pragma unroll
        for (int s = 0; s < 8; ++s) v[s] = vn[s];
    }
#undef LOAD_TILE
}

extern "C" void kernel_launch(void* const* d_in, const int* in_sizes, int n_in,
                              void* d_out, int out_size)
{
    const float* x = (const float*)d_in[0];   // (128, 4, 65536)
    const float* b = (const float*)d_in[1];   // (4, 5)
    const float* a = (const float*)d_in[2];   // (4, 5)
    float* y = (float*)d_out;

    int n_channels = in_sizes[0] / T_LEN;         // 512
    int n_warps    = n_channels * WARPS_PER_CH;   // 2048
    int n_blocks   = n_warps / WPB;               // 256

    iir_filterbank_kernel<<<n_blocks, THREADS>>>(x, b, a, y);
}